// round 10
// baseline (speedup 1.0000x reference)
#include <cuda_runtime.h>
#include <math.h>

// InstanceAwarePointMatching — memset + fused tile kernel + col merge.
//   score = exp(msm) [P,R,S]; row top-3 along s; col top-3 along r.
//   score_map = 0.5*(ref+src); corr_map = (row_hit|col_hit) & refm & srcm.
// Masks arrive as 4-byte elements (uint32 != 0).
//
// fused_tile: block per (p, 64-row chunk). Loads the 64xS tile to smem ONCE
// (16 independent LDG.128 per thread -> MLP 16), computes FINAL row top-3
// (full row in-tile; LDS.128 + max4 prefilter) + col partial top-4 (4-row
// groups). Row results scattered with plain stores (unique writer, runs after
// memset). Col partials -> scratch; col_merge_scatter merges 4 chunks,
// exp-reranks, atomicAdds on top.
//
// Top-k exactness: top-4 on RAW scores ordered (v desc, idx asc); 4 finalists
// re-ranked by (expf desc, idx asc); top-3 kept. Matches jax.lax.top_k over
// exp() including float32 exp-rounding ties. All scans ascend in index and
// prefilters use >=, so ties resolve lowest-index-first.
//
// Smem stride S+16 (=272 for S=256; 272 % 32 == 16):
//   load-store STS.128:  bank 4g            -> conflict-free
//   row scan LDS.128:    bank 16rl+4sub+16j -> phase lanes rl{0,1}: disjoint
//   col scan scalar:     bank 16r+s         -> conflict-free

#define CH      64
#define NCHUNK  4            // R / CH
#define MAX_PART (1 << 19)   // >= P*NCHUNK*S = 524288

__device__ float4 g_pv[MAX_PART];
__device__ int4   g_pi[MAX_PART];

struct T4 { float v0, v1, v2, v3; int i0, i1, i2, i3; };

__device__ __forceinline__ bool better(float v, int i, float w, int j) {
    return (v > w) || (v == w && (unsigned)i < (unsigned)j);
}

__device__ __forceinline__ void t4_init(T4& t) {
    t.v0 = t.v1 = t.v2 = t.v3 = -INFINITY;
    t.i0 = t.i1 = t.i2 = t.i3 = 0x7FFFFFFF;
}

__device__ __forceinline__ void t4_insert(T4& t, float v, int i) {
    if (better(v, i, t.v3, t.i3)) {
        if (better(v, i, t.v2, t.i2)) {
            t.v3 = t.v2; t.i3 = t.i2;
            if (better(v, i, t.v1, t.i1)) {
                t.v2 = t.v1; t.i2 = t.i1;
                if (better(v, i, t.v0, t.i0)) {
                    t.v1 = t.v0; t.i1 = t.i0;
                    t.v0 = v; t.i0 = i;
                } else { t.v1 = v; t.i1 = i; }
            } else { t.v2 = v; t.i2 = i; }
        } else { t.v3 = v; t.i3 = i; }
    }
}

// Re-rank 4 raw finalists by (expf desc, idx asc); emit top-3.
__device__ __forceinline__ void finalize3(const T4& t, float* ev, int* ei) {
    float e[4] = { expf(t.v0), expf(t.v1), expf(t.v2), expf(t.v3) };
    int   x[4] = { t.i0, t.i1, t.i2, t.i3 };
    #pragma unroll
    for (int a = 1; a < 4; a++) {
        #pragma unroll
        for (int b = a; b > 0; b--) {
            if (better(e[b], x[b], e[b-1], x[b-1])) {
                float tv = e[b]; e[b] = e[b-1]; e[b-1] = tv;
                int   ti = x[b]; x[b] = x[b-1]; x[b-1] = ti;
            }
        }
    }
    ev[0] = e[0]; ev[1] = e[1]; ev[2] = e[2];
    ei[0] = x[0]; ei[1] = x[1]; ei[2] = x[2];
}

// ---------------------------------------------------------------------------
// Fused tile: block = (p, r-chunk). 256 threads. Dynamic smem CH*(S+16) floats.
// ---------------------------------------------------------------------------
template <typename CorrT>
__global__ void fused_tile(const float* __restrict__ msm,
                           const unsigned int* __restrict__ refm,
                           const unsigned int* __restrict__ srcm,
                           float* __restrict__ score_out,
                           CorrT* __restrict__ corr_out,
                           int P, int R, int S)
{
    extern __shared__ float tile[];          // [CH][S+16]
    const int stride = S + 16;
    const int bx = blockIdx.x;               // p*NCHUNK + c
    const int c  = bx % NCHUNK;
    const int p  = bx / NCHUNK;
    const int rbase = c * CH;
    const int tid  = threadIdx.x;
    const int lane = tid & 31;
    const int wid  = tid >> 5;

    // ---- load tile: coalesced, MLP-16 independent LDG.128 ----
    if (S == 256) {
        const float4* __restrict__ src =
            (const float4*)(msm + ((size_t)p * R + rbase) * S);
        const int g   = tid & 63;            // float4 column 0..63
        const int rl0 = tid >> 6;            // 0..3
        float4 v[16];
        #pragma unroll
        for (int k = 0; k < 16; k++) {
            v[k] = __ldg(src + (rl0 + (k << 2)) * 64 + g);
        }
        #pragma unroll
        for (int k = 0; k < 16; k++) {
            *((float4*)&tile[(rl0 + (k << 2)) * stride + (g << 2)]) = v[k];
        }
    } else {
        // generic fallback
        const float4* __restrict__ src =
            (const float4*)(msm + ((size_t)p * R + rbase) * S);
        const int sq = S >> 2;
        const int nq = CH * sq;
        for (int q = tid; q < nq; q += blockDim.x) {
            const float4 v = __ldg(src + q);
            const int rl = q / sq;
            const int gg = q - rl * sq;
            *((float4*)&tile[rl * stride + (gg << 2)]) = v;
        }
    }
    __syncthreads();

    // ---- row top-k: 4 lanes per row, 8 rows per warp, LDS.128 + prefilter ----
    {
        const int row_local = (wid << 3) + (lane >> 2);   // 0..CH-1
        const int sub = lane & 3;
        const float* __restrict__ rp = &tile[row_local * stride];
        const int nje = (S >> 4);            // float4-groups per lane (16 for S=256)

        T4 t; t4_init(t);
        #pragma unroll 16
        for (int j = 0; j < nje; j++) {
            const int f4i = sub + (j << 2);            // float4 index 0..63
            const float4 v = *((const float4*)&rp[f4i << 2]);
            const float mx = fmaxf(fmaxf(v.x, v.y), fmaxf(v.z, v.w));
            if (mx >= t.v3) {
                const int s0 = f4i << 2;
                t4_insert(t, v.x, s0);
                t4_insert(t, v.y, s0 + 1);
                t4_insert(t, v.z, s0 + 2);
                t4_insert(t, v.w, s0 + 3);
            }
        }
        // merge across the 4-lane group (disjoint index sets)
        #pragma unroll
        for (int off = 1; off <= 2; off <<= 1) {
            float v0 = __shfl_xor_sync(0xFFFFFFFFu, t.v0, off);
            float v1 = __shfl_xor_sync(0xFFFFFFFFu, t.v1, off);
            float v2 = __shfl_xor_sync(0xFFFFFFFFu, t.v2, off);
            float v3 = __shfl_xor_sync(0xFFFFFFFFu, t.v3, off);
            int   i0 = __shfl_xor_sync(0xFFFFFFFFu, t.i0, off);
            int   i1 = __shfl_xor_sync(0xFFFFFFFFu, t.i1, off);
            int   i2 = __shfl_xor_sync(0xFFFFFFFFu, t.i2, off);
            int   i3 = __shfl_xor_sync(0xFFFFFFFFu, t.i3, off);
            t4_insert(t, v0, i0);
            t4_insert(t, v1, i1);
            t4_insert(t, v2, i2);
            t4_insert(t, v3, i3);
        }

        if (sub == 0) {
            float ev[3]; int ei[3];
            finalize3(t, ev, ei);
            const int rowg = p * R + rbase + row_local;   // global (p,r) id
            const bool rm = __ldg(refm + rowg) != 0u;
            #pragma unroll
            for (int k = 0; k < 3; k++) {
                const int s = ei[k];
                if ((unsigned)s < (unsigned)S) {
                    score_out[(size_t)rowg * S + s] = 0.5f * ev[k];
                    if (rm && __ldg(srcm + (size_t)p * S + s) != 0u) {
                        corr_out[(size_t)rowg * S + s] = (CorrT)1;
                    }
                }
            }
        }
    }

    // ---- col partial top-4: thread per column, 4-row groups + prefilter ----
    {
        const int s = tid;                   // blockDim.x == S assumed (256)
        T4 t; t4_init(t);
        #pragma unroll 16
        for (int g = 0; g < (CH >> 2); g++) {
            const int r0 = g << 2;
            const float f0 = tile[(r0 + 0) * stride + s];
            const float f1 = tile[(r0 + 1) * stride + s];
            const float f2 = tile[(r0 + 2) * stride + s];
            const float f3 = tile[(r0 + 3) * stride + s];
            const float mx = fmaxf(fmaxf(f0, f1), fmaxf(f2, f3));
            if (mx >= t.v3) {
                t4_insert(t, f0, rbase + r0);
                t4_insert(t, f1, rbase + r0 + 1);
                t4_insert(t, f2, rbase + r0 + 2);
                t4_insert(t, f3, rbase + r0 + 3);
            }
        }
        const int q = bx * S + s;
        g_pv[q] = make_float4(t.v0, t.v1, t.v2, t.v3);
        g_pi[q] = make_int4(t.i0, t.i1, t.i2, t.i3);
    }
}

// ---------------------------------------------------------------------------
// Col merge + scatter: thread per (p,s). Coalesced scratch reads, atomicAdd
// on top of the fused kernel's row stores.
// ---------------------------------------------------------------------------
template <typename CorrT>
__global__ void col_merge_scatter(const unsigned int* __restrict__ refm,
                                  const unsigned int* __restrict__ srcm,
                                  float* __restrict__ score_out,
                                  CorrT* __restrict__ corr_out,
                                  int P, int R, int S)
{
    const int idx = (int)(blockIdx.x * (size_t)blockDim.x + threadIdx.x);
    if (idx >= P * S) return;
    const int p = idx / S;
    const int s = idx - p * S;

    T4 t; t4_init(t);
    #pragma unroll
    for (int c = 0; c < NCHUNK; c++) {
        const int q = (p * NCHUNK + c) * S + s;
        const float4 v = g_pv[q];
        const int4   i = g_pi[q];
        t4_insert(t, v.x, i.x);
        t4_insert(t, v.y, i.y);
        t4_insert(t, v.z, i.z);
        t4_insert(t, v.w, i.w);
    }

    float ev[3]; int ei[3];
    finalize3(t, ev, ei);
    const bool sm = __ldg(srcm + idx) != 0u;
    #pragma unroll
    for (int q = 0; q < 3; q++) {
        const int r = ei[q];
        if ((unsigned)r < (unsigned)R) {
            atomicAdd(&score_out[((size_t)p * R + r) * S + s], 0.5f * ev[q]);
            if (sm && __ldg(refm + (size_t)p * R + r) != 0u) {
                corr_out[((size_t)p * R + r) * S + s] = (CorrT)1;
            }
        }
    }
}

extern "C" void kernel_launch(void* const* d_in, const int* in_sizes, int n_in,
                              void* d_out, int out_size)
{
    const float*        msm  = (const float*)d_in[0];
    // d_in[1] = node_corr_scores (unused: conditional=False)
    const unsigned int* refm = (const unsigned int*)d_in[2];   // bool -> 4-byte
    const unsigned int* srcm = (const unsigned int*)d_in[3];   // bool -> 4-byte

    const int P = in_sizes[1];
    const int R = in_sizes[2] / P;
    const int S = in_sizes[3] / P;
    const size_t N = (size_t)P * R * S;

    float* score_out = (float*)d_out;

    const int fused_blocks = P * NCHUNK;            // R/CH chunks per p
    const int fused_tpb = 256;                      // == S
    const size_t smem = (size_t)CH * (S + 16) * sizeof(float);
    const int mrg_tpb = 256;
    const int mrg_blocks = (P * S + mrg_tpb - 1) / mrg_tpb;

    if ((size_t)out_size == 2 * N) {
        // [score_map (f32) | corr_map (f32)]
        cudaFuncSetAttribute(fused_tile<float>,
                             cudaFuncAttributeMaxDynamicSharedMemorySize,
                             (int)smem);
        cudaMemsetAsync(d_out, 0, 2 * N * sizeof(float), 0);
        float* corr_out = score_out + N;
        fused_tile<float><<<fused_blocks, fused_tpb, smem>>>(
            msm, refm, srcm, score_out, corr_out, P, R, S);
        col_merge_scatter<float><<<mrg_blocks, mrg_tpb>>>(
            refm, srcm, score_out, corr_out, P, R, S);
    } else {
        // [score_map (f32) | corr_map (u8)]
        cudaFuncSetAttribute(fused_tile<unsigned char>,
                             cudaFuncAttributeMaxDynamicSharedMemorySize,
                             (int)smem);
        cudaMemsetAsync(d_out, 0, N * sizeof(float) + N, 0);
        unsigned char* corr_out = (unsigned char*)d_out + N * sizeof(float);
        fused_tile<unsigned char><<<fused_blocks, fused_tpb, smem>>>(
            msm, refm, srcm, score_out, corr_out, P, R, S);
        col_merge_scatter<unsigned char><<<mrg_blocks, mrg_tpb>>>(
            refm, srcm, score_out, corr_out, P, R, S);
    }
}

// round 11
// speedup vs baseline: 1.5423x; 1.5423x over previous
#include <cuda_runtime.h>
#include <math.h>
#include <stdint.h>

// InstanceAwarePointMatching — memset + fused tile kernel + col merge.
//   score = exp(msm) [P,R,S]; row top-3 along s; col top-3 along r.
//   score_map = 0.5*(ref+src); corr_map = (row_hit|col_hit) & refm & srcm.
// Masks arrive as 4-byte elements (uint32 != 0).
//
// fused_tile: block per (p, 64-row chunk). Tile -> smem via cp.async (16x16B
// per thread, MLP16, ZERO staging registers — the R10 register-batch load
// spilled and regressed). Row top-3 finalized in-tile (LDS.128 + max4
// prefilter, unroll capped at 4); col partial top-4 (4-row groups, unroll 4).
// Row results: plain stores (unique writer, after memset). Col partials ->
// scratch; col_merge_scatter merges 4 chunks, exp-reranks, atomicAdds on top.
//
// Top-k exactness: top-4 on RAW scores ordered (v desc, idx asc); 4 finalists
// re-ranked by (expf desc, idx asc); top-3 kept. Matches jax.lax.top_k over
// exp() including float32 exp-rounding ties. Scans ascend in index and
// prefilters use >=, so ties resolve lowest-index-first.
//
// Smem stride S+16 (=272 for S=256; 272 % 32 == 16): cp.async stores, row-scan
// LDS.128 phases, and col-scan scalar reads are all bank-conflict-free.

#define CH      64
#define NCHUNK  4            // R / CH
#define MAX_PART (1 << 19)   // >= P*NCHUNK*S = 524288

__device__ float4 g_pv[MAX_PART];
__device__ int4   g_pi[MAX_PART];

struct T4 { float v0, v1, v2, v3; int i0, i1, i2, i3; };

__device__ __forceinline__ bool better(float v, int i, float w, int j) {
    return (v > w) || (v == w && (unsigned)i < (unsigned)j);
}

__device__ __forceinline__ void t4_init(T4& t) {
    t.v0 = t.v1 = t.v2 = t.v3 = -INFINITY;
    t.i0 = t.i1 = t.i2 = t.i3 = 0x7FFFFFFF;
}

__device__ __forceinline__ void t4_insert(T4& t, float v, int i) {
    if (better(v, i, t.v3, t.i3)) {
        if (better(v, i, t.v2, t.i2)) {
            t.v3 = t.v2; t.i3 = t.i2;
            if (better(v, i, t.v1, t.i1)) {
                t.v2 = t.v1; t.i2 = t.i1;
                if (better(v, i, t.v0, t.i0)) {
                    t.v1 = t.v0; t.i1 = t.i0;
                    t.v0 = v; t.i0 = i;
                } else { t.v1 = v; t.i1 = i; }
            } else { t.v2 = v; t.i2 = i; }
        } else { t.v3 = v; t.i3 = i; }
    }
}

// Re-rank 4 raw finalists by (expf desc, idx asc); emit top-3.
__device__ __forceinline__ void finalize3(const T4& t, float* ev, int* ei) {
    float e[4] = { expf(t.v0), expf(t.v1), expf(t.v2), expf(t.v3) };
    int   x[4] = { t.i0, t.i1, t.i2, t.i3 };
    #pragma unroll
    for (int a = 1; a < 4; a++) {
        #pragma unroll
        for (int b = a; b > 0; b--) {
            if (better(e[b], x[b], e[b-1], x[b-1])) {
                float tv = e[b]; e[b] = e[b-1]; e[b-1] = tv;
                int   ti = x[b]; x[b] = x[b-1]; x[b-1] = ti;
            }
        }
    }
    ev[0] = e[0]; ev[1] = e[1]; ev[2] = e[2];
    ei[0] = x[0]; ei[1] = x[1]; ei[2] = x[2];
}

__device__ __forceinline__ void cp_async16(uint32_t smem_dst, const void* gmem_src) {
    asm volatile("cp.async.cg.shared.global [%0], [%1], 16;"
                 :: "r"(smem_dst), "l"(gmem_src));
}
__device__ __forceinline__ void cp_async_wait_all() {
    asm volatile("cp.async.commit_group;\n\tcp.async.wait_group 0;" ::: "memory");
}

// ---------------------------------------------------------------------------
// Fused tile: block = (p, r-chunk). 256 threads. Dynamic smem CH*(S+16) floats.
// ---------------------------------------------------------------------------
template <typename CorrT>
__global__ void __launch_bounds__(256)
fused_tile(const float* __restrict__ msm,
           const unsigned int* __restrict__ refm,
           const unsigned int* __restrict__ srcm,
           float* __restrict__ score_out,
           CorrT* __restrict__ corr_out,
           int P, int R, int S)
{
    extern __shared__ float tile[];          // [CH][S+16]
    const int stride = S + 16;
    const int bx = blockIdx.x;               // p*NCHUNK + c
    const int c  = bx % NCHUNK;
    const int p  = bx / NCHUNK;
    const int rbase = c * CH;
    const int tid  = threadIdx.x;
    const int lane = tid & 31;
    const int wid  = tid >> 5;

    // ---- load tile: cp.async, 16 independent 16B copies, no staging regs ----
    if (S == 256) {
        const float* __restrict__ srcf =
            msm + ((size_t)p * R + rbase) * S;
        const int g   = tid & 63;            // float4 column 0..63
        const int rl0 = tid >> 6;            // 0..3
        const uint32_t smem_base =
            (uint32_t)__cvta_generic_to_shared(tile);
        #pragma unroll
        for (int k = 0; k < 16; k++) {
            const int rl = rl0 + (k << 2);
            cp_async16(smem_base + (uint32_t)((rl * stride + (g << 2)) * 4),
                       srcf + (size_t)rl * 256 + (g << 2));
        }
        cp_async_wait_all();
    } else {
        const float4* __restrict__ src =
            (const float4*)(msm + ((size_t)p * R + rbase) * S);
        const int sq = S >> 2;
        const int nq = CH * sq;
        for (int q = tid; q < nq; q += blockDim.x) {
            const float4 v = __ldg(src + q);
            const int rl = q / sq;
            const int gg = q - rl * sq;
            *((float4*)&tile[rl * stride + (gg << 2)]) = v;
        }
    }
    __syncthreads();

    // ---- row top-k: 4 lanes per row, 8 rows per warp, LDS.128 + prefilter ----
    {
        const int row_local = (wid << 3) + (lane >> 2);   // 0..CH-1
        const int sub = lane & 3;
        const float* __restrict__ rp = &tile[row_local * stride];
        const int nje = (S >> 4);            // float4-groups per lane

        T4 t; t4_init(t);
        #pragma unroll 4
        for (int j = 0; j < nje; j++) {
            const int f4i = sub + (j << 2);            // float4 index
            const float4 v = *((const float4*)&rp[f4i << 2]);
            const float mx = fmaxf(fmaxf(v.x, v.y), fmaxf(v.z, v.w));
            if (mx >= t.v3) {
                const int s0 = f4i << 2;
                t4_insert(t, v.x, s0);
                t4_insert(t, v.y, s0 + 1);
                t4_insert(t, v.z, s0 + 2);
                t4_insert(t, v.w, s0 + 3);
            }
        }
        // merge across the 4-lane group (disjoint index sets)
        #pragma unroll
        for (int off = 1; off <= 2; off <<= 1) {
            float v0 = __shfl_xor_sync(0xFFFFFFFFu, t.v0, off);
            float v1 = __shfl_xor_sync(0xFFFFFFFFu, t.v1, off);
            float v2 = __shfl_xor_sync(0xFFFFFFFFu, t.v2, off);
            float v3 = __shfl_xor_sync(0xFFFFFFFFu, t.v3, off);
            int   i0 = __shfl_xor_sync(0xFFFFFFFFu, t.i0, off);
            int   i1 = __shfl_xor_sync(0xFFFFFFFFu, t.i1, off);
            int   i2 = __shfl_xor_sync(0xFFFFFFFFu, t.i2, off);
            int   i3 = __shfl_xor_sync(0xFFFFFFFFu, t.i3, off);
            t4_insert(t, v0, i0);
            t4_insert(t, v1, i1);
            t4_insert(t, v2, i2);
            t4_insert(t, v3, i3);
        }

        if (sub == 0) {
            float ev[3]; int ei[3];
            finalize3(t, ev, ei);
            const int rowg = p * R + rbase + row_local;   // global (p,r) id
            const bool rm = __ldg(refm + rowg) != 0u;
            #pragma unroll
            for (int k = 0; k < 3; k++) {
                const int s = ei[k];
                if ((unsigned)s < (unsigned)S) {
                    score_out[(size_t)rowg * S + s] = 0.5f * ev[k];
                    if (rm && __ldg(srcm + (size_t)p * S + s) != 0u) {
                        corr_out[(size_t)rowg * S + s] = (CorrT)1;
                    }
                }
            }
        }
    }

    // ---- col partial top-4: thread per column, 4-row groups + prefilter ----
    {
        const int s = tid;                   // blockDim.x == S assumed (256)
        T4 t; t4_init(t);
        #pragma unroll 4
        for (int g = 0; g < (CH >> 2); g++) {
            const int r0 = g << 2;
            const float f0 = tile[(r0 + 0) * stride + s];
            const float f1 = tile[(r0 + 1) * stride + s];
            const float f2 = tile[(r0 + 2) * stride + s];
            const float f3 = tile[(r0 + 3) * stride + s];
            const float mx = fmaxf(fmaxf(f0, f1), fmaxf(f2, f3));
            if (mx >= t.v3) {
                t4_insert(t, f0, rbase + r0);
                t4_insert(t, f1, rbase + r0 + 1);
                t4_insert(t, f2, rbase + r0 + 2);
                t4_insert(t, f3, rbase + r0 + 3);
            }
        }
        const int q = bx * S + s;
        g_pv[q] = make_float4(t.v0, t.v1, t.v2, t.v3);
        g_pi[q] = make_int4(t.i0, t.i1, t.i2, t.i3);
    }
}

// ---------------------------------------------------------------------------
// Col merge + scatter: thread per (p,s). Coalesced scratch reads, atomicAdd
// on top of the fused kernel's row stores.
// ---------------------------------------------------------------------------
template <typename CorrT>
__global__ void col_merge_scatter(const unsigned int* __restrict__ refm,
                                  const unsigned int* __restrict__ srcm,
                                  float* __restrict__ score_out,
                                  CorrT* __restrict__ corr_out,
                                  int P, int R, int S)
{
    const int idx = (int)(blockIdx.x * (size_t)blockDim.x + threadIdx.x);
    if (idx >= P * S) return;
    const int p = idx / S;
    const int s = idx - p * S;

    T4 t; t4_init(t);
    #pragma unroll
    for (int c = 0; c < NCHUNK; c++) {
        const int q = (p * NCHUNK + c) * S + s;
        const float4 v = g_pv[q];
        const int4   i = g_pi[q];
        t4_insert(t, v.x, i.x);
        t4_insert(t, v.y, i.y);
        t4_insert(t, v.z, i.z);
        t4_insert(t, v.w, i.w);
    }

    float ev[3]; int ei[3];
    finalize3(t, ev, ei);
    const bool sm = __ldg(srcm + idx) != 0u;
    #pragma unroll
    for (int q = 0; q < 3; q++) {
        const int r = ei[q];
        if ((unsigned)r < (unsigned)R) {
            atomicAdd(&score_out[((size_t)p * R + r) * S + s], 0.5f * ev[q]);
            if (sm && __ldg(refm + (size_t)p * R + r) != 0u) {
                corr_out[((size_t)p * R + r) * S + s] = (CorrT)1;
            }
        }
    }
}

extern "C" void kernel_launch(void* const* d_in, const int* in_sizes, int n_in,
                              void* d_out, int out_size)
{
    const float*        msm  = (const float*)d_in[0];
    // d_in[1] = node_corr_scores (unused: conditional=False)
    const unsigned int* refm = (const unsigned int*)d_in[2];   // bool -> 4-byte
    const unsigned int* srcm = (const unsigned int*)d_in[3];   // bool -> 4-byte

    const int P = in_sizes[1];
    const int R = in_sizes[2] / P;
    const int S = in_sizes[3] / P;
    const size_t N = (size_t)P * R * S;

    float* score_out = (float*)d_out;

    const int fused_blocks = P * NCHUNK;            // R/CH chunks per p
    const int fused_tpb = 256;                      // == S
    const size_t smem = (size_t)CH * (S + 16) * sizeof(float);
    const int mrg_tpb = 256;
    const int mrg_blocks = (P * S + mrg_tpb - 1) / mrg_tpb;

    if ((size_t)out_size == 2 * N) {
        // [score_map (f32) | corr_map (f32)]
        cudaFuncSetAttribute(fused_tile<float>,
                             cudaFuncAttributeMaxDynamicSharedMemorySize,
                             (int)smem);
        cudaMemsetAsync(d_out, 0, 2 * N * sizeof(float), 0);
        float* corr_out = score_out + N;
        fused_tile<float><<<fused_blocks, fused_tpb, smem>>>(
            msm, refm, srcm, score_out, corr_out, P, R, S);
        col_merge_scatter<float><<<mrg_blocks, mrg_tpb>>>(
            refm, srcm, score_out, corr_out, P, R, S);
    } else {
        // [score_map (f32) | corr_map (u8)]
        cudaFuncSetAttribute(fused_tile<unsigned char>,
                             cudaFuncAttributeMaxDynamicSharedMemorySize,
                             (int)smem);
        cudaMemsetAsync(d_out, 0, N * sizeof(float) + N, 0);
        unsigned char* corr_out = (unsigned char*)d_out + N * sizeof(float);
        fused_tile<unsigned char><<<fused_blocks, fused_tpb, smem>>>(
            msm, refm, srcm, score_out, corr_out, P, R, S);
        col_merge_scatter<unsigned char><<<mrg_blocks, mrg_tpb>>>(
            refm, srcm, score_out, corr_out, P, R, S);
    }
}